// round 15
// baseline (speedup 1.0000x reference)
#include <cuda_runtime.h>
#include <cuda_fp16.h>
#include <cstdint>

#define Nn 100000
#define Ee 1600000
#define Dd 128
#define SCAN_BLOCKS ((Nn + 1023) / 1024)   // 98
#define NCHUNK 12
#define RW 64   // half2 words per feature row (= 16 uint4)

// ---- scratch (device globals: allocation-free rule) ----
// g_deg / g_cnt are zero at module load and re-zeroed by k_spmm_csr pass 1
// (after their last read in k_scan), so the fused prep+count kernel never races.
__device__ int                g_deg[Nn];
__device__ int                g_cnt[Nn];
__device__ float              g_dis[Nn];
__device__ int                g_rowptr[Nn + 1];
__device__ unsigned long long g_state[SCAN_BLOCKS];   // lookback: flag(hi32) | value(lo32)
__device__ int                g_rank[Ee];              // within-row rank of each edge
__device__ int                g_csr_i[Ee];             // src only
__device__ uint32_t           g_Wh[NCHUNK * 128 * 16]; // half2, kmap-permuted; chunks 0-3 = W0-W2
__device__ uint32_t           g_x0 [(size_t)Nn * RW];  // half2(x), permuted (25.6 MB)
__device__ uint32_t           g_Tx1[(size_t)Nn * RW];
__device__ uint32_t           g_Tx2[(size_t)Nn * RW];  // holds T2' = -2 P(Tx1)

__device__ __forceinline__ uint32_t smem_u32(const void* p) {
    uint32_t a;
    asm("{ .reg .u64 t; cvta.to.shared.u64 t, %1; cvt.u32.u64 %0, t; }" : "=r"(a) : "l"(p));
    return a;
}

__device__ __forceinline__ uint32_t packh2(float a, float b) {
    __half2 h = __floats2half2_rn(a, b);
    return *reinterpret_cast<uint32_t*>(&h);
}
__device__ __forceinline__ float2 unpackh2(uint32_t u) {
    __half2 h = *reinterpret_cast<__half2*>(&u);
    return __half22float2(h);
}
__device__ __forceinline__ uint32_t hfma2u(uint32_t a, uint32_t b, uint32_t c) {
    __half2 r = __hfma2(*reinterpret_cast<__half2*>(&a),
                        *reinterpret_cast<__half2*>(&b),
                        *reinterpret_cast<__half2*>(&c));
    return *reinterpret_cast<uint32_t*>(&r);
}

// inverse kmap on k-pairs: word p in [0,16) -> kp
__device__ __forceinline__ int inv_kmap(int p) {
    return ((p >> 3) << 3) + ((p & 1) << 2) + ((p & 7) >> 1);
}

// ====== fused: W prep (W0-W2 fold) + x prep + degree count + rank + scan-state reset ======
__global__ void k_prep(const float* __restrict__ x, const float* __restrict__ W,
                       const int* __restrict__ ei) {
    int i = blockIdx.x * blockDim.x + threadIdx.x;
    if (i < SCAN_BLOCKS) g_state[i] = 0ULL;
    if (i < NCHUNK * 128 * 16) {
        int chunk = i >> 11;
        int n     = (i >> 4) & 127;
        int p     = i & 15;
        int kp = inv_kmap(p);
        int k  = chunk * 32 + 2 * kp;
        float w0 = W[k * Dd + n];
        float w1 = W[(k + 1) * Dd + n];
        if (chunk < 4) {           // W0' = W0 - W2  (fold: Tx2 = T2' - x0)
            w0 -= W[(k + 256) * Dd + n];
            w1 -= W[(k + 257) * Dd + n];
        }
        g_Wh[i] = packh2(w0, w1);
    }
    if (i < Nn * RW) {
        int row = i >> 6;
        int w   = i & 63;
        int cc  = w >> 4;
        int p   = w & 15;
        int kp  = inv_kmap(p);
        int k   = cc * 32 + 2 * kp;
        g_x0[i] = packh2(x[(size_t)row * Dd + k], x[(size_t)row * Dd + k + 1]);
    }
    if (i < Ee) {
        int s = ei[i];
        int d = ei[Ee + i];
        if (s != d) {
            atomicAdd(&g_deg[s], 1);
            g_rank[i] = atomicAdd(&g_cnt[d], 1);   // rank within dst row
        }
    }
}

// ====== single-pass scan: block-local scan + decoupled lookback (+ dis fused) ======
__global__ void k_scan() {
    __shared__ int sh[1024];
    __shared__ int s_excl;
    int t = threadIdx.x;
    int b = blockIdx.x;
    int i = b * 1024 + t;
    int v = (i < Nn) ? g_cnt[i] : 0;
    if (i < Nn) {
        int dg = g_deg[i];
        g_dis[i] = (dg > 0) ? rsqrtf((float)dg) : 0.f;
    }
    sh[t] = v;
    __syncthreads();
    #pragma unroll
    for (int off = 1; off < 1024; off <<= 1) {
        int u = (t >= off) ? sh[t - off] : 0;
        __syncthreads();
        sh[t] += u;
        __syncthreads();
    }
    int total = sh[1023];

    if (t == 0) {
        if (b == 0) {
            atomicExch(&g_state[0], (2ULL << 32) | (unsigned)total);   // INCLUSIVE ready
            s_excl = 0;
        } else {
            atomicExch(&g_state[b], (1ULL << 32) | (unsigned)total);   // AGGREGATE ready
            int excl = 0;
            int p = b - 1;
            while (true) {
                unsigned long long st = atomicAdd(&g_state[p], 0ULL);  // atomic read
                unsigned flag = (unsigned)(st >> 32);
                if (flag == 2u) { excl += (int)(unsigned)st; break; }
                if (flag == 1u) { excl += (int)(unsigned)st; p--; }
            }
            atomicExch(&g_state[b], (2ULL << 32) | (unsigned)(excl + total));
            s_excl = excl;
        }
    }
    __syncthreads();
    int excl = s_excl;
    if (i < Nn) g_rowptr[i] = sh[t] - v + excl;                 // exclusive global prefix
    if (b == SCAN_BLOCKS - 1 && t == 1023) g_rowptr[Nn] = excl + total;
}

// ---- fill: atomic-free via precomputed rank ----
__global__ void k_fill(const int* __restrict__ ei) {
    int e = blockIdx.x * blockDim.x + threadIdx.x;
    if (e < Ee) {
        int s = ei[e];
        int d = ei[Ee + e];
        if (s != d)
            g_csr_i[g_rowptr[d] + g_rank[e]] = s;
    }
}

// ====== CSR SPMM (fp16 features, chained HFMA2 + fp32 block-flush, 2 edges/warp) ======
// out[r] = h2( alpha*dis[r]*Sum_j dis[s_j]*feat[s_j] + beta*xin[r] )
// 4-edge half2 accumulation chains, flushed to fp32 once per 32-edge block segment.
// zero_cnt: pass 1 re-zeroes g_deg/g_cnt for the next graph replay.
__global__ void __launch_bounds__(256, 7)
k_spmm_csr(const uint4* __restrict__ feat, const uint4* __restrict__ xin,
           uint4* __restrict__ out, float alpha, float beta, int zero_cnt) {
    int w = (blockIdx.x * blockDim.x + threadIdx.x) >> 5;
    int lane = threadIdx.x & 31;
    int li   = lane & 15;
    int half = lane >> 4;
    if (w >= Nn) return;

    if (zero_cnt && lane == 0) { g_deg[w] = 0; g_cnt[w] = 0; }

    int start = g_rowptr[w];
    int end   = g_rowptr[w + 1];

    float acc[8];
    #pragma unroll
    for (int i = 0; i < 8; i++) acc[i] = 0.f;

    for (int base = start; base < end; base += 32) {
        int j = base + lane;
        int sj = 0; uint32_t wh2 = 0u;
        if (j < end) {
            sj = g_csr_i[j];
            __half hw = __float2half_rn(g_dis[sj]);
            __half2 h2 = __half2half2(hw);
            wh2 = *reinterpret_cast<uint32_t*>(&h2);
        }
        int m = end - base; if (m > 32) m = 32;

        int k = 0;
        for (; k + 8 <= m; k += 8) {            // 4 edges per half-warp, fp16 chain
            uint32_t hacc[4] = {0u, 0u, 0u, 0u};
            #pragma unroll
            for (int p = 0; p < 4; p++) {
                int e = k + 2 * p + half;
                int      s  = __shfl_sync(~0u, sj, e);
                uint32_t wg = __shfl_sync(~0u, wh2, e);
                uint4 v = __ldg(&feat[(size_t)s * 16 + li]);
                hacc[0] = hfma2u(v.x, wg, hacc[0]);
                hacc[1] = hfma2u(v.y, wg, hacc[1]);
                hacc[2] = hfma2u(v.z, wg, hacc[2]);
                hacc[3] = hfma2u(v.w, wg, hacc[3]);
            }
            #pragma unroll
            for (int i = 0; i < 4; i++) {
                float2 f = unpackh2(hacc[i]);
                acc[2 * i] += f.x; acc[2 * i + 1] += f.y;
            }
        }
        if (k < m) {                            // remainder: <=3 edges per half, fp16 chain
            uint32_t hacc[4] = {0u, 0u, 0u, 0u};
            for (; k < m; k += 2) {
                int e = k + half;
                int      s  = __shfl_sync(~0u, sj, e);
                uint32_t wg = __shfl_sync(~0u, wh2, e);
                uint4 v = __ldg(&feat[(size_t)s * 16 + li]);
                hacc[0] = hfma2u(v.x, wg, hacc[0]);
                hacc[1] = hfma2u(v.y, wg, hacc[1]);
                hacc[2] = hfma2u(v.z, wg, hacc[2]);
                hacc[3] = hfma2u(v.w, wg, hacc[3]);
            }
            #pragma unroll
            for (int i = 0; i < 4; i++) {
                float2 f = unpackh2(hacc[i]);
                acc[2 * i] += f.x; acc[2 * i + 1] += f.y;
            }
        }
    }

    // combine the two half-warps
    #pragma unroll
    for (int i = 0; i < 8; i++) acc[i] += __shfl_xor_sync(~0u, acc[i], 16);

    if (half == 0) {
        float scale = alpha * g_dis[w];
        float r[8];
        if (beta != 0.f) {
            uint4 xv = xin[(size_t)w * 16 + li];
            float2 x0 = unpackh2(xv.x), x1 = unpackh2(xv.y);
            float2 x2 = unpackh2(xv.z), x3 = unpackh2(xv.w);
            r[0] = scale * acc[0] + beta * x0.x; r[1] = scale * acc[1] + beta * x0.y;
            r[2] = scale * acc[2] + beta * x1.x; r[3] = scale * acc[3] + beta * x1.y;
            r[4] = scale * acc[4] + beta * x2.x; r[5] = scale * acc[5] + beta * x2.y;
            r[6] = scale * acc[6] + beta * x3.x; r[7] = scale * acc[7] + beta * x3.y;
        } else {
            #pragma unroll
            for (int i = 0; i < 8; i++) r[i] = scale * acc[i];
        }
        uint4 o;
        o.x = packh2(r[0], r[1]); o.y = packh2(r[2], r[3]);
        o.z = packh2(r[4], r[5]); o.w = packh2(r[6], r[7]);
        out[(size_t)w * 16 + li] = o;
    }
}

// ================= FP16 GEMM (mma.m16n8k16, fp32 accum, cp.async 3-stage) =================
__device__ __forceinline__ void mma_f16(float& d0, float& d1, float& d2, float& d3,
                                        uint32_t a0, uint32_t a1, uint32_t a2, uint32_t a3,
                                        uint32_t b0, uint32_t b1) {
    asm volatile("mma.sync.aligned.m16n8k16.row.col.f32.f16.f16.f32 "
                 "{%0,%1,%2,%3}, {%4,%5,%6,%7}, {%8,%9}, {%0,%1,%2,%3};\n"
                 : "+f"(d0), "+f"(d1), "+f"(d2), "+f"(d3)
                 : "r"(a0), "r"(a1), "r"(a2), "r"(a3), "r"(b0), "r"(b1));
}

__device__ __forceinline__ void cp16cg(uint32_t smaddr, const void* g) {
    asm volatile("cp.async.cg.shared.global [%0], [%1], 16;"
                 :: "r"(smaddr), "l"(g) : "memory");
}
template <int N>
__device__ __forceinline__ void cp_wait() {
    asm volatile("cp.async.wait_group %0;" :: "n"(N) : "memory");
}

#define STR16 20                      // smem row stride (words)
#define AWORDS (128 * STR16)          // 2560
#define STGW   (2 * AWORDS)           // 5120 words / stage
#define NSTAGE 3
#define GEMM_SMEM (NSTAGE * STGW * 4) // 61440 bytes

__global__ void __launch_bounds__(256, 2)
k_gemm(const float* __restrict__ bias, float* __restrict__ out) {
    extern __shared__ uint32_t sm[];
    uint32_t smb = smem_u32(sm);
    int t = threadIdx.x;
    int lane = t & 31;
    int wid = t >> 5;
    int wm = (wid & 3) * 32;
    int wn = (wid >> 2) * 64;
    int row0 = blockIdx.x * 128;

    float acc[2][8][4];
    #pragma unroll
    for (int mi = 0; mi < 2; mi++)
        #pragma unroll
        for (int ni = 0; ni < 8; ni++)
            #pragma unroll
            for (int q = 0; q < 4; q++) acc[mi][ni][q] = 0.f;

    auto docopy = [&](int chunk, int st) {
        const uint32_t* A = (chunk < 4) ? g_x0 : (chunk < 8) ? g_Tx1 : g_Tx2;
        int wl0 = (chunk & 3) * 16;
        uint32_t base = smb + st * (STGW * 4);
        #pragma unroll
        for (int i = 0; i < 2; i++) {
            int idx = t + i * 256;
            int r = idx >> 2;
            int q = idx & 3;
            int grow = row0 + r;
            if (grow > Nn - 1) grow = Nn - 1;
            cp16cg(base + (r * STR16 + q * 4) * 4, A + (size_t)grow * RW + wl0 + q * 4);
            cp16cg(base + (AWORDS + r * STR16 + q * 4) * 4,
                   g_Wh + ((size_t)chunk * 128 + r) * 16 + q * 4);
        }
        asm volatile("cp.async.commit_group;" ::: "memory");
    };

    docopy(0, 0);
    docopy(1, 1);

    for (int n = 0; n < NCHUNK; n++) {
        if (n < NCHUNK - 1) cp_wait<1>(); else cp_wait<0>();
        __syncthreads();
        if (n + 2 < NCHUNK) docopy(n + 2, (n + 2) % NSTAGE);

        const uint32_t* Asm = sm + (n % NSTAGE) * STGW;
        const uint32_t* Bsm = Asm + AWORDS;
        #pragma unroll
        for (int ks = 0; ks < 2; ks++) {
            int cw = ks * 8 + (lane & 3) * 2;
            uint32_t a[2][4];
            #pragma unroll
            for (int mi = 0; mi < 2; mi++) {
                int r = wm + mi * 16 + (lane >> 2);
                uint2 lo = *(const uint2*)&Asm[r * STR16 + cw];
                uint2 hi = *(const uint2*)&Asm[(r + 8) * STR16 + cw];
                a[mi][0] = lo.x; a[mi][2] = lo.y;
                a[mi][1] = hi.x; a[mi][3] = hi.y;
            }
            uint32_t b[8][2];
            #pragma unroll
            for (int ni = 0; ni < 8; ni++) {
                int nb = wn + ni * 8 + (lane >> 2);
                uint2 bv = *(const uint2*)&Bsm[nb * STR16 + cw];
                b[ni][0] = bv.x; b[ni][1] = bv.y;
            }
            #pragma unroll
            for (int mi = 0; mi < 2; mi++)
                #pragma unroll
                for (int ni = 0; ni < 8; ni++)
                    mma_f16(acc[mi][ni][0], acc[mi][ni][1], acc[mi][ni][2], acc[mi][ni][3],
                            a[mi][0], a[mi][1], a[mi][2], a[mi][3],
                            b[ni][0], b[ni][1]);
        }
    }

    #pragma unroll
    for (int mi = 0; mi < 2; mi++) {
        int r0 = row0 + wm + mi * 16 + (lane >> 2);
        #pragma unroll
        for (int ni = 0; ni < 8; ni++) {
            int c = wn + ni * 8 + (lane & 3) * 2;
            float b0 = __ldg(&bias[c]);
            float b1 = __ldg(&bias[c + 1]);
            if (r0 < Nn) {
                float2 o = make_float2(acc[mi][ni][0] + b0, acc[mi][ni][1] + b1);
                *(float2*)(out + (size_t)r0 * Dd + c) = o;
            }
            if (r0 + 8 < Nn) {
                float2 o = make_float2(acc[mi][ni][2] + b0, acc[mi][ni][3] + b1);
                *(float2*)(out + (size_t)(r0 + 8) * Dd + c) = o;
            }
        }
    }
}

extern "C" void kernel_launch(void* const* d_in, const int* in_sizes, int n_in,
                              void* d_out, int out_size) {
    const float* x    = (const float*)d_in[0];
    const int*   ei   = (const int*)d_in[1];
    const float* W    = (const float*)d_in[2];
    const float* bias = (const float*)d_in[3];
    float* out = (float*)d_out;
    (void)in_sizes; (void)n_in; (void)out_size;

    uint4* X0;  cudaGetSymbolAddress((void**)&X0,  g_x0);
    uint4* Tx1; cudaGetSymbolAddress((void**)&Tx1, g_Tx1);
    uint4* Tx2; cudaGetSymbolAddress((void**)&Tx2, g_Tx2);

    cudaFuncSetAttribute(k_gemm, cudaFuncAttributeMaxDynamicSharedMemorySize, GEMM_SMEM);

    k_prep <<<(Nn * RW + 255) / 256, 256>>>(x, W, ei);            // 1 (prep + count + rank)
    k_scan <<<SCAN_BLOCKS, 1024>>>();                             // 2 (single-pass lookback)
    k_fill <<<(Ee + 255) / 256, 256>>>(ei);                       // 3 (atomic-free)

    // Tx1 = -(dis_d * Sum dis_s * x0_s)   [also re-zeroes deg/cnt for next replay]
    k_spmm_csr<<<(Nn * 32 + 255) / 256, 256>>>(X0, X0, Tx1, -1.0f, 0.0f, 1);   // 4 (ncu slot)
    // Tx2' = -2*(dis_d * Sum dis_s * Tx1_s)     (x0 folded into W0' = W0 - W2)
    k_spmm_csr<<<(Nn * 32 + 255) / 256, 256>>>(Tx1, X0, Tx2, -2.0f, 0.0f, 0);  // 5

    // out = x0@(W0-W2) + Tx1@W1 + Tx2'@W2 + bias
    k_gemm<<<(Nn + 127) / 128, 256, GEMM_SMEM>>>(bias, out);      // 6
}

// round 16
// speedup vs baseline: 1.1542x; 1.1542x over previous
#include <cuda_runtime.h>
#include <cuda_fp16.h>
#include <cstdint>

#define Nn 100000
#define Ee 1600000
#define Dd 128
#define SCAN_BLOCKS ((Nn + 1023) / 1024)   // 98
#define NCHUNK 12
#define RW 64   // half2 words per feature row (= 16 uint4)

// ---- scratch (device globals: allocation-free rule) ----
// g_deg / g_cnt are zero at module load and re-zeroed by k_spmm_csr pass 1
// (after their last read in k_scan), so the fused prep+count kernel never races.
__device__ int                g_deg[Nn];
__device__ int                g_cnt[Nn];
__device__ float              g_dis[Nn];
__device__ int                g_rowptr[Nn + 1];
__device__ unsigned long long g_state[SCAN_BLOCKS];   // lookback: flag(hi32) | value(lo32)
__device__ int                g_rank[Ee];              // within-row rank of each edge
__device__ int2               g_csr[Ee];               // {src, w_bits = dis[src] fp32}
__device__ uint32_t           g_Wh[NCHUNK * 128 * 16]; // half2, kmap-permuted; chunks 0-3 = W0-W2
__device__ uint32_t           g_x0 [(size_t)Nn * RW];  // half2(x), permuted (25.6 MB)
__device__ uint32_t           g_Tx1[(size_t)Nn * RW];
__device__ uint32_t           g_Tx2[(size_t)Nn * RW];  // holds T2' = -2 P(Tx1)

__device__ __forceinline__ uint32_t smem_u32(const void* p) {
    uint32_t a;
    asm("{ .reg .u64 t; cvta.to.shared.u64 t, %1; cvt.u32.u64 %0, t; }" : "=r"(a) : "l"(p));
    return a;
}

__device__ __forceinline__ uint32_t packh2(float a, float b) {
    __half2 h = __floats2half2_rn(a, b);
    return *reinterpret_cast<uint32_t*>(&h);
}
__device__ __forceinline__ float2 unpackh2(uint32_t u) {
    __half2 h = *reinterpret_cast<__half2*>(&u);
    return __half22float2(h);
}

// inverse kmap on k-pairs: word p in [0,16) -> kp
__device__ __forceinline__ int inv_kmap(int p) {
    return ((p >> 3) << 3) + ((p & 1) << 2) + ((p & 7) >> 1);
}

// ====== fused: W prep (W0-W2 fold) + x prep + degree count + rank + scan-state reset ======
__global__ void k_prep(const float* __restrict__ x, const float* __restrict__ W,
                       const int* __restrict__ ei) {
    int i = blockIdx.x * blockDim.x + threadIdx.x;
    if (i < SCAN_BLOCKS) g_state[i] = 0ULL;
    if (i < NCHUNK * 128 * 16) {
        int chunk = i >> 11;
        int n     = (i >> 4) & 127;
        int p     = i & 15;
        int kp = inv_kmap(p);
        int k  = chunk * 32 + 2 * kp;
        float w0 = W[k * Dd + n];
        float w1 = W[(k + 1) * Dd + n];
        if (chunk < 4) {           // W0' = W0 - W2  (fold: Tx2 = T2' - x0)
            w0 -= W[(k + 256) * Dd + n];
            w1 -= W[(k + 257) * Dd + n];
        }
        g_Wh[i] = packh2(w0, w1);
    }
    if (i < Nn * RW) {
        int row = i >> 6;
        int w   = i & 63;
        int cc  = w >> 4;
        int p   = w & 15;
        int kp  = inv_kmap(p);
        int k   = cc * 32 + 2 * kp;
        g_x0[i] = packh2(x[(size_t)row * Dd + k], x[(size_t)row * Dd + k + 1]);
    }
    if (i < Ee) {
        int s = ei[i];
        int d = ei[Ee + i];
        if (s != d) {
            atomicAdd(&g_deg[s], 1);
            g_rank[i] = atomicAdd(&g_cnt[d], 1);   // rank within dst row
        }
    }
}

// ====== single-pass scan: block-local scan + decoupled lookback (+ dis fused) ======
__global__ void k_scan() {
    __shared__ int sh[1024];
    __shared__ int s_excl;
    int t = threadIdx.x;
    int b = blockIdx.x;
    int i = b * 1024 + t;
    int v = (i < Nn) ? g_cnt[i] : 0;
    if (i < Nn) {
        int dg = g_deg[i];
        g_dis[i] = (dg > 0) ? rsqrtf((float)dg) : 0.f;
    }
    sh[t] = v;
    __syncthreads();
    #pragma unroll
    for (int off = 1; off < 1024; off <<= 1) {
        int u = (t >= off) ? sh[t - off] : 0;
        __syncthreads();
        sh[t] += u;
        __syncthreads();
    }
    int total = sh[1023];

    if (t == 0) {
        if (b == 0) {
            atomicExch(&g_state[0], (2ULL << 32) | (unsigned)total);   // INCLUSIVE ready
            s_excl = 0;
        } else {
            atomicExch(&g_state[b], (1ULL << 32) | (unsigned)total);   // AGGREGATE ready
            int excl = 0;
            int p = b - 1;
            while (true) {
                unsigned long long st = atomicAdd(&g_state[p], 0ULL);  // atomic read
                unsigned flag = (unsigned)(st >> 32);
                if (flag == 2u) { excl += (int)(unsigned)st; break; }
                if (flag == 1u) { excl += (int)(unsigned)st; p--; }
            }
            atomicExch(&g_state[b], (2ULL << 32) | (unsigned)(excl + total));
            s_excl = excl;
        }
    }
    __syncthreads();
    int excl = s_excl;
    if (i < Nn) g_rowptr[i] = sh[t] - v + excl;                 // exclusive global prefix
    if (b == SCAN_BLOCKS - 1 && t == 1023) g_rowptr[Nn] = excl + total;
}

// ---- fill: atomic-free via precomputed rank; embeds dis[src] in the CSR entry ----
__global__ void k_fill(const int* __restrict__ ei) {
    int e = blockIdx.x * blockDim.x + threadIdx.x;
    if (e < Ee) {
        int s = ei[e];
        int d = ei[Ee + e];
        if (s != d) {
            float w = g_dis[s];
            g_csr[g_rowptr[d] + g_rank[e]] = make_int2(s, __float_as_int(w));
        }
    }
}

// ====== CSR SPMM (fp16 features, fp32 accum, 2 edges per warp, weight in CSR) ======
// out[r] = h2( alpha*dis[r]*Sum_j w_j*feat[s_j] + beta*xin[r] ),  w_j = dis[s_j]
// zero_cnt: pass 1 re-zeroes g_deg/g_cnt for the next graph replay.
__global__ void __launch_bounds__(256, 7)
k_spmm_csr(const uint4* __restrict__ feat, const uint4* __restrict__ xin,
           uint4* __restrict__ out, float alpha, float beta, int zero_cnt) {
    int w = (blockIdx.x * blockDim.x + threadIdx.x) >> 5;
    int lane = threadIdx.x & 31;
    int li   = lane & 15;
    int half = lane >> 4;
    if (w >= Nn) return;

    if (zero_cnt && lane == 0) { g_deg[w] = 0; g_cnt[w] = 0; }

    int start = g_rowptr[w];
    int end   = g_rowptr[w + 1];

    float acc[8];
    #pragma unroll
    for (int i = 0; i < 8; i++) acc[i] = 0.f;

    for (int base = start; base < end; base += 32) {
        int j = base + lane;
        int sj = 0; float wj = 0.f;
        if (j < end) {
            int2 ed = g_csr[j];                 // single coalesced LDG.64
            sj = ed.x;
            wj = __int_as_float(ed.y);
        }
        int m = end - base; if (m > 32) m = 32;

        int k = 0;
        for (; k + 8 <= m; k += 8) {            // 4 edge-pairs, MLP=4
            #pragma unroll
            for (int p = 0; p < 4; p++) {
                int e = k + 2 * p + half;
                int   s   = __shfl_sync(~0u, sj, e);
                float wgt = __shfl_sync(~0u, wj, e);
                uint4 v = __ldg(&feat[(size_t)s * 16 + li]);
                float2 c0 = unpackh2(v.x), c1 = unpackh2(v.y);
                float2 c2 = unpackh2(v.z), c3 = unpackh2(v.w);
                acc[0] += wgt * c0.x; acc[1] += wgt * c0.y;
                acc[2] += wgt * c1.x; acc[3] += wgt * c1.y;
                acc[4] += wgt * c2.x; acc[5] += wgt * c2.y;
                acc[6] += wgt * c3.x; acc[7] += wgt * c3.y;
            }
        }
        for (; k < m; k += 2) {                 // pair remainder (w=0 pads)
            int e = k + half;
            int   s   = __shfl_sync(~0u, sj, e);
            float wgt = __shfl_sync(~0u, wj, e);
            uint4 v = __ldg(&feat[(size_t)s * 16 + li]);
            float2 c0 = unpackh2(v.x), c1 = unpackh2(v.y);
            float2 c2 = unpackh2(v.z), c3 = unpackh2(v.w);
            acc[0] += wgt * c0.x; acc[1] += wgt * c0.y;
            acc[2] += wgt * c1.x; acc[3] += wgt * c1.y;
            acc[4] += wgt * c2.x; acc[5] += wgt * c2.y;
            acc[6] += wgt * c3.x; acc[7] += wgt * c3.y;
        }
    }

    // combine the two half-warps
    #pragma unroll
    for (int i = 0; i < 8; i++) acc[i] += __shfl_xor_sync(~0u, acc[i], 16);

    if (half == 0) {
        float scale = alpha * g_dis[w];
        float r[8];
        if (beta != 0.f) {
            uint4 xv = xin[(size_t)w * 16 + li];
            float2 x0 = unpackh2(xv.x), x1 = unpackh2(xv.y);
            float2 x2 = unpackh2(xv.z), x3 = unpackh2(xv.w);
            r[0] = scale * acc[0] + beta * x0.x; r[1] = scale * acc[1] + beta * x0.y;
            r[2] = scale * acc[2] + beta * x1.x; r[3] = scale * acc[3] + beta * x1.y;
            r[4] = scale * acc[4] + beta * x2.x; r[5] = scale * acc[5] + beta * x2.y;
            r[6] = scale * acc[6] + beta * x3.x; r[7] = scale * acc[7] + beta * x3.y;
        } else {
            #pragma unroll
            for (int i = 0; i < 8; i++) r[i] = scale * acc[i];
        }
        uint4 o;
        o.x = packh2(r[0], r[1]); o.y = packh2(r[2], r[3]);
        o.z = packh2(r[4], r[5]); o.w = packh2(r[6], r[7]);
        out[(size_t)w * 16 + li] = o;
    }
}

// ================= FP16 GEMM (mma.m16n8k16, fp32 accum, cp.async 3-stage) =================
__device__ __forceinline__ void mma_f16(float& d0, float& d1, float& d2, float& d3,
                                        uint32_t a0, uint32_t a1, uint32_t a2, uint32_t a3,
                                        uint32_t b0, uint32_t b1) {
    asm volatile("mma.sync.aligned.m16n8k16.row.col.f32.f16.f16.f32 "
                 "{%0,%1,%2,%3}, {%4,%5,%6,%7}, {%8,%9}, {%0,%1,%2,%3};\n"
                 : "+f"(d0), "+f"(d1), "+f"(d2), "+f"(d3)
                 : "r"(a0), "r"(a1), "r"(a2), "r"(a3), "r"(b0), "r"(b1));
}

__device__ __forceinline__ void cp16cg(uint32_t smaddr, const void* g) {
    asm volatile("cp.async.cg.shared.global [%0], [%1], 16;"
                 :: "r"(smaddr), "l"(g) : "memory");
}
template <int N>
__device__ __forceinline__ void cp_wait() {
    asm volatile("cp.async.wait_group %0;" :: "n"(N) : "memory");
}

#define STR16 20                      // smem row stride (words)
#define AWORDS (128 * STR16)          // 2560
#define STGW   (2 * AWORDS)           // 5120 words / stage
#define NSTAGE 3
#define GEMM_SMEM (NSTAGE * STGW * 4) // 61440 bytes

__global__ void __launch_bounds__(256, 2)
k_gemm(const float* __restrict__ bias, float* __restrict__ out) {
    extern __shared__ uint32_t sm[];
    uint32_t smb = smem_u32(sm);
    int t = threadIdx.x;
    int lane = t & 31;
    int wid = t >> 5;
    int wm = (wid & 3) * 32;
    int wn = (wid >> 2) * 64;
    int row0 = blockIdx.x * 128;

    float acc[2][8][4];
    #pragma unroll
    for (int mi = 0; mi < 2; mi++)
        #pragma unroll
        for (int ni = 0; ni < 8; ni++)
            #pragma unroll
            for (int q = 0; q < 4; q++) acc[mi][ni][q] = 0.f;

    auto docopy = [&](int chunk, int st) {
        const uint32_t* A = (chunk < 4) ? g_x0 : (chunk < 8) ? g_Tx1 : g_Tx2;
        int wl0 = (chunk & 3) * 16;
        uint32_t base = smb + st * (STGW * 4);
        #pragma unroll
        for (int i = 0; i < 2; i++) {
            int idx = t + i * 256;
            int r = idx >> 2;
            int q = idx & 3;
            int grow = row0 + r;
            if (grow > Nn - 1) grow = Nn - 1;
            cp16cg(base + (r * STR16 + q * 4) * 4, A + (size_t)grow * RW + wl0 + q * 4);
            cp16cg(base + (AWORDS + r * STR16 + q * 4) * 4,
                   g_Wh + ((size_t)chunk * 128 + r) * 16 + q * 4);
        }
        asm volatile("cp.async.commit_group;" ::: "memory");
    };

    docopy(0, 0);
    docopy(1, 1);

    for (int n = 0; n < NCHUNK; n++) {
        if (n < NCHUNK - 1) cp_wait<1>(); else cp_wait<0>();
        __syncthreads();
        if (n + 2 < NCHUNK) docopy(n + 2, (n + 2) % NSTAGE);

        const uint32_t* Asm = sm + (n % NSTAGE) * STGW;
        const uint32_t* Bsm = Asm + AWORDS;
        #pragma unroll
        for (int ks = 0; ks < 2; ks++) {
            int cw = ks * 8 + (lane & 3) * 2;
            uint32_t a[2][4];
            #pragma unroll
            for (int mi = 0; mi < 2; mi++) {
                int r = wm + mi * 16 + (lane >> 2);
                uint2 lo = *(const uint2*)&Asm[r * STR16 + cw];
                uint2 hi = *(const uint2*)&Asm[(r + 8) * STR16 + cw];
                a[mi][0] = lo.x; a[mi][2] = lo.y;
                a[mi][1] = hi.x; a[mi][3] = hi.y;
            }
            uint32_t b[8][2];
            #pragma unroll
            for (int ni = 0; ni < 8; ni++) {
                int nb = wn + ni * 8 + (lane >> 2);
                uint2 bv = *(const uint2*)&Bsm[nb * STR16 + cw];
                b[ni][0] = bv.x; b[ni][1] = bv.y;
            }
            #pragma unroll
            for (int mi = 0; mi < 2; mi++)
                #pragma unroll
                for (int ni = 0; ni < 8; ni++)
                    mma_f16(acc[mi][ni][0], acc[mi][ni][1], acc[mi][ni][2], acc[mi][ni][3],
                            a[mi][0], a[mi][1], a[mi][2], a[mi][3],
                            b[ni][0], b[ni][1]);
        }
    }

    #pragma unroll
    for (int mi = 0; mi < 2; mi++) {
        int r0 = row0 + wm + mi * 16 + (lane >> 2);
        #pragma unroll
        for (int ni = 0; ni < 8; ni++) {
            int c = wn + ni * 8 + (lane & 3) * 2;
            float b0 = __ldg(&bias[c]);
            float b1 = __ldg(&bias[c + 1]);
            if (r0 < Nn) {
                float2 o = make_float2(acc[mi][ni][0] + b0, acc[mi][ni][1] + b1);
                *(float2*)(out + (size_t)r0 * Dd + c) = o;
            }
            if (r0 + 8 < Nn) {
                float2 o = make_float2(acc[mi][ni][2] + b0, acc[mi][ni][3] + b1);
                *(float2*)(out + (size_t)(r0 + 8) * Dd + c) = o;
            }
        }
    }
}

extern "C" void kernel_launch(void* const* d_in, const int* in_sizes, int n_in,
                              void* d_out, int out_size) {
    const float* x    = (const float*)d_in[0];
    const int*   ei   = (const int*)d_in[1];
    const float* W    = (const float*)d_in[2];
    const float* bias = (const float*)d_in[3];
    float* out = (float*)d_out;
    (void)in_sizes; (void)n_in; (void)out_size;

    uint4* X0;  cudaGetSymbolAddress((void**)&X0,  g_x0);
    uint4* Tx1; cudaGetSymbolAddress((void**)&Tx1, g_Tx1);
    uint4* Tx2; cudaGetSymbolAddress((void**)&Tx2, g_Tx2);

    cudaFuncSetAttribute(k_gemm, cudaFuncAttributeMaxDynamicSharedMemorySize, GEMM_SMEM);

    k_prep <<<(Nn * RW + 255) / 256, 256>>>(x, W, ei);            // 1 (prep + count + rank)
    k_scan <<<SCAN_BLOCKS, 1024>>>();                             // 2 (single-pass lookback)
    k_fill <<<(Ee + 255) / 256, 256>>>(ei);                       // 3 (atomic-free, embeds w)

    // Tx1 = -(dis_d * Sum w_s * x0_s)   [also re-zeroes deg/cnt for next replay]
    k_spmm_csr<<<(Nn * 32 + 255) / 256, 256>>>(X0, X0, Tx1, -1.0f, 0.0f, 1);   // 4 (ncu slot)
    // Tx2' = -2*(dis_d * Sum w_s * Tx1_s)     (x0 folded into W0' = W0 - W2)
    k_spmm_csr<<<(Nn * 32 + 255) / 256, 256>>>(Tx1, X0, Tx2, -2.0f, 0.0f, 0);  // 5

    // out = x0@(W0-W2) + Tx1@W1 + Tx2'@W2 + bias
    k_gemm<<<(Nn + 127) / 128, 256, GEMM_SMEM>>>(bias, out);      // 6
}